// round 14
// baseline (speedup 1.0000x reference)
#include <cuda_runtime.h>
#include <cuda_fp16.h>
#include <cstdint>

// ---------------- problem constants ----------------
#define HID        256
#define OBS_STRIDE 54
#define SELF_OBS   18
#define NBR        6
#define BATCH_N    131072
#define TILE_B     16                    // batches per CTA iteration
#define NTILES     (BATCH_N / TILE_B)    // 8192
#define THREADS    512                   // 16 warps = 8 K-split pairs
#define GRID_X     152

// smem layout: exch | pexch | xs
#define EXCH_BYTES  (2 * NBR * 16 * 32 * 16)      // 98304: [buf][nb][chunk][lane] uint4
#define PEXCH_BYTES (8 * 2 * 2 * 2 * 32 * 16)     // 32768: [pair][nbuf][parity][j][lane] float4
#define XS_OFF      (EXCH_BYTES + PEXCH_BYTES)
#define XS_STRIDE   42
#define XS_BYTES    (2 * TILE_B * XS_STRIDE * 4)  // 5376
#define SMEM_BYTES  (XS_OFF + XS_BYTES)           // 136448

// ==================== helpers ====================
static __device__ __forceinline__ float tanha(float x) {
    float y;
    asm("tanh.approx.f32 %0, %1;" : "=f"(y) : "f"(x));
    return y;
}
static __device__ __forceinline__ uint32_t packh2(float a, float b) {
    __half2 h = __floats2half2_rn(a, b);
    return *reinterpret_cast<uint32_t*>(&h);
}
// D[16x8] += A[16x8] * B[8x8]   (f16 in, f32 accum)
static __device__ __forceinline__ void mma_k8(float& d0, float& d1, float& d2, float& d3,
                                              uint32_t a0, uint32_t a1, uint32_t b0) {
    asm volatile("mma.sync.aligned.m16n8k8.row.col.f32.f16.f16.f32 "
                 "{%0,%1,%2,%3}, {%4,%5}, {%6}, {%0,%1,%2,%3};"
                 : "+f"(d0), "+f"(d1), "+f"(d2), "+f"(d3)
                 : "r"(a0), "r"(a1), "r"(b0));
}
// D[16x8] += A[16x16] * B[16x8]
static __device__ __forceinline__ void mma_k16(float* d,
                                               uint32_t a0, uint32_t a1, uint32_t a2, uint32_t a3,
                                               uint32_t b0, uint32_t b1) {
    asm volatile("mma.sync.aligned.m16n8k16.row.col.f32.f16.f16.f32 "
                 "{%0,%1,%2,%3}, {%4,%5,%6,%7}, {%8,%9}, {%0,%1,%2,%3};"
                 : "+f"(d[0]), "+f"(d[1]), "+f"(d[2]), "+f"(d[3])
                 : "r"(a0), "r"(a1), "r"(a2), "r"(a3), "r"(b0), "r"(b1));
}

// ==================== kernel ====================
__global__ void __launch_bounds__(THREADS, 1)
deepsets_kernel(const float* __restrict__ obs,
                const float* __restrict__ W1,
                const float* __restrict__ b1,
                const float* __restrict__ W2,
                const float* __restrict__ b2,
                float* __restrict__ out)
{
    extern __shared__ char smem[];
    uint4*  exch = reinterpret_cast<uint4*>(smem);
    float4* pex  = reinterpret_cast<float4*>(smem + EXCH_BYTES);
    float*  xsf  = reinterpret_cast<float*>(smem + XS_OFF);

    const int tid  = threadIdx.x;
    const int w    = tid >> 5;
    const int lane = tid & 31;
    const int gid  = lane >> 2;
    const int tig  = lane & 3;
    const int g    = w >> 1;        // K-split pair id (0..7), pair covers cols [32g, 32g+32)
    const int p    = w & 1;         // K-half parity: k in [128p, 128p+128)
    const int n0   = w * 16;        // own output cols [16w, 16w+16) (== 32g + 16p)
    const bool sodd = (w >> 2) & 1; // phase stagger, constant within pairs, alternates per SMSP

    // ---- resident W1 B-fragments + layer-1 bias (warp w produces chunk w: hidden 16w..16w+16)
    uint32_t w1b[2];
    float2 b1v[2], b2v[2];
    #pragma unroll
    for (int j = 0; j < 2; j++) {
        int tt = 2 * w + j;
        int n  = tt * 8 + gid;
        int c  = tt * 8 + 2 * tig;
        w1b[j] = (tig < 3) ? packh2(W1[2 * tig * HID + n], W1[(2 * tig + 1) * HID + n]) : 0u;
        b1v[j] = make_float2(b1[c], b1[c + 1]);
        b2v[j] = make_float2(b2[c], b2[c + 1]);   // own output cols == produced chunk cols
    }

    // ---- resident W2 B-fragments: K-half [128p,128p+128) x pair cols [32g,32g+32) (64 regs)
    uint32_t blo[8][4], bhi[8][4];
    #pragma unroll
    for (int c = 0; c < 8; c++) {
        #pragma unroll
        for (int t = 0; t < 4; t++) {
            int n = 32 * g + t * 8 + gid;
            int k = (p * 8 + c) * 16 + 2 * tig;
            blo[c][t] = packh2(W2[k * HID + n],       W2[(k + 1) * HID + n]);
            bhi[c][t] = packh2(W2[(k + 8) * HID + n], W2[(k + 9) * HID + n]);
        }
    }

    const float inv6 = 1.0f / 6.0f;

    auto xstage = [&](long b0, int pb) {
        for (int i = tid; i < TILE_B * 18; i += THREADS) {
            int r = i / 18, c2 = i % 18;
            float2 v = *reinterpret_cast<const float2*>(&obs[(b0 + r) * OBS_STRIDE + SELF_OBS + 2 * c2]);
            *reinterpret_cast<float2*>(&xsf[(pb * TILE_B + r) * XS_STRIDE + 2 * c2]) = v;
        }
    };

    // layer-1 for neighbor nb of the tile staged in xs[pb] -> exch[buf] chunk w
    auto layer1 = [&](int nb, int pb, int buf) {
        uint32_t xa0 = 0u, xa1 = 0u;
        if (tig < 3) {
            const float* q = &xsf[(pb * TILE_B + gid) * XS_STRIDE + nb * 6 + 2 * tig];
            float2 v0 = *reinterpret_cast<const float2*>(q);
            float2 v1 = *reinterpret_cast<const float2*>(q + 8 * XS_STRIDE);
            xa0 = packh2(v0.x, v0.y);
            xa1 = packh2(v1.x, v1.y);
        }
        uint4 pk;
        uint32_t* pkr = reinterpret_cast<uint32_t*>(&pk);
        #pragma unroll
        for (int j = 0; j < 2; j++) {
            float d0 = 0.f, d1 = 0.f, d2 = 0.f, d3 = 0.f;
            mma_k8(d0, d1, d2, d3, xa0, xa1, w1b[j]);
            pkr[j * 2 + 0] = packh2(tanha(d0 + b1v[j].x), tanha(d1 + b1v[j].y));
            pkr[j * 2 + 1] = packh2(tanha(d2 + b1v[j].x), tanha(d3 + b1v[j].y));
        }
        exch[((buf * NBR + nb) * 16 + w) * 32 + lane] = pk;
    };

    // ---- prologue ----
    {
        long t0 = (long)blockIdx.x;
        xstage(t0 * TILE_B, 0);
        if (t0 + GRID_X < NTILES) xstage((t0 + GRID_X) * TILE_B, 1);
        __syncthreads();
        #pragma unroll
        for (int nb = 0; nb < NBR; nb++) layer1(nb, 0, 0);
    }
    __syncthreads();

    int buf = 0;
    for (int tile = blockIdx.x; tile < NTILES; tile += gridDim.x) {
        const long b0     = (long)tile * TILE_B;
        const bool has_nx = (tile + gridDim.x < NTILES);
        const bool has_n2 = (tile + 2 * gridDim.x < NTILES);

        if (has_n2) xstage((long)(tile + 2 * gridDim.x) * TILE_B, buf);

        float acc[2][4];
        #pragma unroll
        for (int t = 0; t < 2; t++)
            #pragma unroll
            for (int i = 0; i < 4; i++) acc[t][i] = 0.0f;

        // burst: partial-K HMMA over 8 chunks, pair partial-exchange, epilogue on own cols
        auto burst = [&](int nb) {
            float D[4][4];
            #pragma unroll
            for (int t = 0; t < 4; t++)
                #pragma unroll
                for (int i = 0; i < 4; i++) D[t][i] = 0.0f;

            // my K-half: global chunks p*8 .. p*8+7
            const uint4* ap = &exch[((buf * NBR + nb) * 16 + p * 8) * 32 + lane];
            #pragma unroll
            for (int c = 0; c < 8; c++) {
                uint4 a = ap[c * 32];
                mma_k16(D[0], a.x, a.y, a.z, a.w, blo[c][0], bhi[c][0]);
                mma_k16(D[1], a.x, a.y, a.z, a.w, blo[c][1], bhi[c][1]);
                mma_k16(D[2], a.x, a.y, a.z, a.w, blo[c][2], bhi[c][2]);
                mma_k16(D[3], a.x, a.y, a.z, a.w, blo[c][3], bhi[c][3]);
            }

            // pair partial exchange: send partner's tiles, keep own (uniform branch,
            // constant indices -> no dynamic register addressing)
            const int nbuf = nb & 1;
            const int wbase = (((g * 2 + nbuf) * 2 + p) * 2) * 32 + lane;
            const int rbase = (((g * 2 + nbuf) * 2 + (p ^ 1)) * 2) * 32 + lane;
            float Do[2][4];
            if (p == 0) {
                pex[wbase]      = make_float4(D[2][0], D[2][1], D[2][2], D[2][3]);
                pex[wbase + 32] = make_float4(D[3][0], D[3][1], D[3][2], D[3][3]);
                #pragma unroll
                for (int i = 0; i < 4; i++) { Do[0][i] = D[0][i]; Do[1][i] = D[1][i]; }
            } else {
                pex[wbase]      = make_float4(D[0][0], D[0][1], D[0][2], D[0][3]);
                pex[wbase + 32] = make_float4(D[1][0], D[1][1], D[1][2], D[1][3]);
                #pragma unroll
                for (int i = 0; i < 4; i++) { Do[0][i] = D[2][i]; Do[1][i] = D[3][i]; }
            }
            asm volatile("bar.sync %0, %1;" :: "r"(1 + g), "r"(64) : "memory");
            float4 q0 = pex[rbase];
            float4 q1 = pex[rbase + 32];

            acc[0][0] += tanha(Do[0][0] + q0.x + b2v[0].x);
            acc[0][1] += tanha(Do[0][1] + q0.y + b2v[0].y);
            acc[0][2] += tanha(Do[0][2] + q0.z + b2v[0].x);
            acc[0][3] += tanha(Do[0][3] + q0.w + b2v[0].y);
            acc[1][0] += tanha(Do[1][0] + q1.x + b2v[1].x);
            acc[1][1] += tanha(Do[1][1] + q1.y + b2v[1].y);
            acc[1][2] += tanha(Do[1][2] + q1.z + b2v[1].x);
            acc[1][3] += tanha(Do[1][3] + q1.w + b2v[1].y);
        };

        // Phase-staggered interleave (parity constant within pairs).
        #pragma unroll
        for (int nb = 0; nb < NBR; nb++) {
            if (sodd) {
                burst(nb);
                if (has_nx) layer1(nb, buf ^ 1, buf ^ 1);
            } else {
                if (has_nx) layer1(nb, buf ^ 1, buf ^ 1);
                burst(nb);
            }
        }

        // ---- mean over neighbors, write out (own cols 16w..16w+16) ----
        #pragma unroll
        for (int t = 0; t < 2; t++) {
            int col = n0 + t * 8 + 2 * tig;
            float2 v0 = make_float2(acc[t][0] * inv6, acc[t][1] * inv6);
            float2 v1 = make_float2(acc[t][2] * inv6, acc[t][3] * inv6);
            *reinterpret_cast<float2*>(&out[(b0 + gid)     * HID + col]) = v0;
            *reinterpret_cast<float2*>(&out[(b0 + gid + 8) * HID + col]) = v1;
        }

        __syncthreads();
        buf ^= 1;
    }
}

// ==================== launch ====================
extern "C" void kernel_launch(void* const* d_in, const int* in_sizes, int n_in,
                              void* d_out, int out_size) {
    // inputs: self_obs(131072*18), obs(131072*54), W1(6*256), b1(256), W2(256*256), b2(256)
    const float* obs = nullptr;
    const float* W1  = nullptr;
    const float* b1  = nullptr;
    const float* W2  = nullptr;
    const float* b2  = nullptr;
    for (int i = 0; i < n_in; i++) {
        int sz = in_sizes[i];
        if (sz == BATCH_N * OBS_STRIDE)  obs = (const float*)d_in[i];
        else if (sz == 6 * HID)          W1  = (const float*)d_in[i];
        else if (sz == HID * HID)        W2  = (const float*)d_in[i];
        else if (sz == HID) {
            if (!b1) b1 = (const float*)d_in[i];
            else if (!b2) b2 = (const float*)d_in[i];
        }
    }
    float* out = (float*)d_out;

    cudaFuncSetAttribute(deepsets_kernel,
                         cudaFuncAttributeMaxDynamicSharedMemorySize, SMEM_BYTES);
    deepsets_kernel<<<GRID_X, THREADS, SMEM_BYTES>>>(obs, W1, b1, W2, b2, out);
}